// round 16
// baseline (speedup 1.0000x reference)
#include <cuda_runtime.h>
#include <cuda_bf16.h>
#include <math.h>
#include <stdint.h>

#define N_CLOUDS 16
#define NCHUNK 126   // K = 8064 = 126 chunks of 64

// ---------------- static scratch (no allocations allowed) ----------------
// A & W stored as contiguous 8KB tiles: tile(mb,kc) = 64 rows x 64 halfs,
// pre-swizzled: half h at row r lives at r*64 + (h ^ ((r&7)<<3)).
__device__ __align__(16) __nv_bfloat16 g_A[(size_t)16384 * 8064];
__device__ __align__(16) float g_x1[32768 * 64];
__device__ __align__(16) float g_x2out[16384 * 64];
__device__ __align__(16) float g_x3out[4096 * 128];
__device__ __align__(16) float g_part[2097152];            // split-K partials (8MB)
__device__ __align__(16) float g_w1f[128 * 64];            // fp32 [k][o] for fused L1
__device__ __align__(16) __nv_bfloat16 g_w2e[64 * 8064];   // tiled [1][126] tiles
__device__ __align__(16) __nv_bfloat16 g_w3e[128 * 8064];  // tiled [2][126] tiles
__device__ __align__(16) float g_pool[N_CLOUDS * 128];
__device__ __align__(16) float g_cnt[N_CLOUDS];

__device__ __forceinline__ int lowerb(const int* __restrict__ a, int n, int v) {
    int lo = 0, hi = n;
    while (lo < hi) { int m = (lo + hi) >> 1; if (a[m] < v) lo = m + 1; else hi = m; }
    return lo;
}

__device__ __forceinline__ float eluf(float v) { return v > 0.f ? v : expm1f(v); }

__device__ __forceinline__ uint32_t s2u(const void* p) {
    return (uint32_t)__cvta_generic_to_shared(p);
}

// ---------------- merged weight prep: w1f (fp32) + w2e/w3e tiled bf16 --------
__global__ void prep_weights(const float* __restrict__ W1, const float* __restrict__ R1,
                             const float* __restrict__ W2, const float* __restrict__ R2,
                             const float* __restrict__ W3, const float* __restrict__ R3,
                             float* __restrict__ w1f, __nv_bfloat16* __restrict__ w2e,
                             __nv_bfloat16* __restrict__ w3e)
{
    const int N1 = 128 * 64, N2 = 64 * 8064, N3 = 128 * 8064;
    int i = blockIdx.x * blockDim.x + threadIdx.x;
    if (i < N1) {
        int k = i >> 6, c = i & 63;
        float v = 0.f;
        if (k < 125) v = W1[k * 64 + c];
        else if (k == 125) v = R1[c];
        w1f[i] = v;
        return;
    }
    i -= N1;
    if (i < N2) {
        int k = i / 64, c = i - k * 64;          // k in K-dim, c = out channel
        float v = 0.f;
        if (k < 8000) v = W2[k * 64 + c];
        else if (k < 8064) v = R2[(k - 8000) * 64 + c];
        int kc = k >> 6, kh = k & 63, r = c & 63;
        w2e[(size_t)kc * 4096 + r * 64 + (kh ^ ((r & 7) << 3))] = __float2bfloat16(v);
        return;
    }
    i -= N2;
    if (i < N3) {
        int k = i / 128, c = i - k * 128;
        float v = 0.f;
        if (k < 8000) v = W3[k * 128 + c];
        else if (k < 8064) v = R3[(k - 8000) * 128 + c];
        int kc = k >> 6, kh = k & 63, nb = c >> 6, r = c & 63;
        w3e[((size_t)nb * NCHUNK + kc) * 4096 + r * 64 + (kh ^ ((r & 7) << 3))] =
            __float2bfloat16(v);
    }
}

// ---------------- layer 1 fused: A build + block-shared-W matvec + ELU -------
// 4 warps = 4 nodes. W1f staged once per block in smem; matvec k-partitioned
// across warps (8 FMA per LDS.64), partials reduced in smem.
__global__ void __launch_bounds__(128) build_x1(
    const float* __restrict__ pos, const int* __restrict__ src,
    const int* __restrict__ tgt, int nE, float inv2r,
    const float* __restrict__ W1f, const float* __restrict__ b1,
    float* __restrict__ x1)
{
    __shared__ float A[4][128];
    __shared__ float Ws[8192];          // 32KB staged W1f
    __shared__ float2 partial[4][4][32];
    __shared__ float invd_s[4];
    int tid = threadIdx.x, warp = tid >> 5, lane = tid & 31;
    int n = blockIdx.x * 4 + warp;

    // stage W (float4, 16 per thread)
    for (int i = tid; i < 2048; i += 128)
        ((float4*)Ws)[i] = ((const float4*)W1f)[i];

    float* Aw = A[warp];
    Aw[lane] = 0.f; Aw[lane + 32] = 0.f; Aw[lane + 64] = 0.f; Aw[lane + 96] = 0.f;
    __syncwarp();
    int s0 = lowerb(tgt, nE, n);
    int s1 = lowerb(tgt, nE, n + 1);
    float tx = pos[n * 3 + 0], ty = pos[n * 3 + 1], tz = pos[n * 3 + 2];
    for (int e = s0 + lane; e < s1; e += 32) {
        int sN = src[e];
        float px = fminf(fmaxf((tx - pos[sN * 3 + 0]) * inv2r + 0.5f, 0.f), 1.f) * 4.f;
        float py = fminf(fmaxf((ty - pos[sN * 3 + 1]) * inv2r + 0.5f, 0.f), 1.f) * 4.f;
        float pz = fminf(fmaxf((tz - pos[sN * 3 + 2]) * inv2r + 0.5f, 0.f), 1.f) * 4.f;
        float bx = floorf(px), by = floorf(py), bz = floorf(pz);
        float fx = px - bx, fy = py - by, fz = pz - bz;
        int ix = (int)bx, iy = (int)by, iz = (int)bz;
#pragma unroll
        for (int s = 0; s < 8; s++) {
            int b0 = s & 1, b1i = (s >> 1) & 1, b2 = s >> 2;
            float w = (b0 ? fx : 1.f - fx) * (b1i ? fy : 1.f - fy) * (b2 ? fz : 1.f - fz);
            int wi = min(ix + b0, 4) + 5 * min(iy + b1i, 4) + 25 * min(iz + b2, 4);
            atomicAdd(&Aw[wi], w);
        }
    }
    __syncwarp();
    if (lane == 0) invd_s[warp] = 1.f / fmaxf((float)(s1 - s0), 1.f);
    __syncthreads();

    // k-partitioned matvec: warp q handles k in [32q, min(32q+32,125))
    int klo = warp * 32, khi = min(klo + 32, 125);
    float2 acc0 = {0.f, 0.f}, acc1 = {0.f, 0.f}, acc2 = {0.f, 0.f}, acc3 = {0.f, 0.f};
    for (int k = klo; k < khi; k++) {
        float2 w2 = *(const float2*)&Ws[k * 64 + 2 * lane];
        float a0 = A[0][k], a1 = A[1][k], a2 = A[2][k], a3 = A[3][k];
        acc0.x += a0 * w2.x; acc0.y += a0 * w2.y;
        acc1.x += a1 * w2.x; acc1.y += a1 * w2.y;
        acc2.x += a2 * w2.x; acc2.y += a2 * w2.y;
        acc3.x += a3 * w2.x; acc3.y += a3 * w2.y;
    }
    partial[warp][0][lane] = acc0;
    partial[warp][1][lane] = acc1;
    partial[warp][2][lane] = acc2;
    partial[warp][3][lane] = acc3;
    __syncthreads();

    // reduce: thread (warp=node, lane=cp)
    float2 r = partial[0][warp][lane];
#pragma unroll
    for (int q = 1; q < 4; q++) {
        float2 p = partial[q][warp][lane];
        r.x += p.x; r.y += p.y;
    }
    float iv = invd_s[warp];
    int o = 2 * lane;
    float v0 = r.x * iv + Ws[125 * 64 + o] + b1[o];        // root (x==1) + bias
    float v1 = r.y * iv + Ws[125 * 64 + o + 1] + b1[o + 1];
    x1[(size_t)n * 64 + o] = eluf(v0);
    x1[(size_t)n * 64 + o + 1] = eluf(v1);
}

// ---------------- layers 2/3 A build: tiled+swizzled A output ----------------
__global__ void __launch_bounds__(64) build_A64(
    const float* __restrict__ xin, const int* __restrict__ xidx,
    const float* __restrict__ pos, const int* __restrict__ pidx1,
    const int* __restrict__ pidx2,
    const int* __restrict__ src, const int* __restrict__ tgt, int nE,
    float inv2r, __nv_bfloat16* __restrict__ Aout)
{
    __shared__ float xj_s[32 * 64];        // 8KB fp32, float2-aligned
    __shared__ float tw[256];
    __shared__ unsigned char twi[256];
    __shared__ float2 ws_srt[256];         // (w, bitcast(j*32))
    __shared__ int cnts[128];              // 125 used + 3 zero pad (scan safety)
    __shared__ int bstart[126];
    __shared__ int cursor[125];
    __shared__ int esrc_s[32];

    int n = blockIdx.x, tid = threadIdx.x;   // 64 threads
    cnts[tid] = 0; cnts[tid + 64] = 0;       // zero all 128
    int s0 = lowerb(tgt, nE, n);
    int s1 = lowerb(tgt, nE, n + 1);
    int cnt = min(s1 - s0, 32);              // max_nb = 32
    float invd = 1.f / fmaxf((float)cnt, 1.f);
    int pn = pidx2 ? pidx1[pidx2[n]] : pidx1[n];
    float tx = pos[pn * 3 + 0], ty = pos[pn * 3 + 1], tz = pos[pn * 3 + 2];
    __syncthreads();
    if (tid < cnt) {
        int sN = src[s0 + tid];
        esrc_s[tid] = xidx[sN];              // resolved x row
        int ps = pidx2 ? pidx1[pidx2[sN]] : pidx1[sN];
        float px = fminf(fmaxf((tx - pos[ps * 3 + 0]) * inv2r + 0.5f, 0.f), 1.f) * 4.f;
        float py = fminf(fmaxf((ty - pos[ps * 3 + 1]) * inv2r + 0.5f, 0.f), 1.f) * 4.f;
        float pz = fminf(fmaxf((tz - pos[ps * 3 + 2]) * inv2r + 0.5f, 0.f), 1.f) * 4.f;
        float bx = floorf(px), by = floorf(py), bz = floorf(pz);
        float fx = px - bx, fy = py - by, fz = pz - bz;
        int ix = (int)bx, iy = (int)by, iz = (int)bz;
#pragma unroll
        for (int s = 0; s < 8; s++) {
            int b0 = s & 1, b1 = (s >> 1) & 1, b2 = s >> 2;
            float w = (b0 ? fx : 1.f - fx) * (b1 ? fy : 1.f - fy) * (b2 ? fz : 1.f - fz);
            int wi = min(ix + b0, 4) + 5 * min(iy + b1, 4) + 25 * min(iz + b2, 4);
            tw[tid * 8 + s] = w * invd;       // fold degree normalization
            twi[tid * 8 + s] = (unsigned char)wi;
            atomicAdd(&cnts[wi], 1);
        }
    }
    __syncthreads();
    // warp-scan prefix over 128 buckets (warp 0; 4 buckets/lane; 125..127 = 0)
    if (tid < 32) {
        int b0i = tid * 4;
        int v0 = cnts[b0i], v1 = cnts[b0i + 1], v2 = cnts[b0i + 2], v3 = cnts[b0i + 3];
        int s = v0 + v1 + v2 + v3;
#pragma unroll
        for (int off = 1; off < 32; off <<= 1) {
            int t = __shfl_up_sync(0xffffffff, s, off);
            if (tid >= off) s += t;
        }
        int base = s - (v0 + v1 + v2 + v3);
        bstart[b0i] = base;
        if (b0i + 1 <= 125) bstart[b0i + 1] = base + v0;
        if (b0i + 2 <= 125) bstart[b0i + 2] = base + v0 + v1;
        if (b0i + 3 <= 125) bstart[b0i + 3] = base + v0 + v1 + v2;
    }
    __syncthreads();
    for (int i = tid; i < 125; i += 64) cursor[i] = bstart[i];
    __syncthreads();
    if (tid < cnt) {
#pragma unroll
        for (int s = 0; s < 8; s++) {
            int wi = twi[tid * 8 + s];
            int p = atomicAdd(&cursor[wi], 1);
            ws_srt[p] = make_float2(tw[tid * 8 + s], __int_as_float(tid * 32));
        }
    }
    // stage xj rows — 4-way unrolled for MLP
    {
        int j = 0;
        for (; j + 4 <= cnt; j += 4) {
            float v0 = xin[(size_t)esrc_s[j] * 64 + tid];
            float v1 = xin[(size_t)esrc_s[j + 1] * 64 + tid];
            float v2 = xin[(size_t)esrc_s[j + 2] * 64 + tid];
            float v3 = xin[(size_t)esrc_s[j + 3] * 64 + tid];
            xj_s[j * 64 + tid] = v0;
            xj_s[(j + 1) * 64 + tid] = v1;
            xj_s[(j + 2) * 64 + tid] = v2;
            xj_s[(j + 3) * 64 + tid] = v3;
        }
        for (; j < cnt; j++)
            xj_s[j * 64 + tid] = xin[(size_t)esrc_s[j] * 64 + tid];
    }
    __syncthreads();

    // tiled + swizzled output
    int r = n & 63;
    int sw = (r & 7) << 3;
    size_t tbase0 = ((size_t)(n >> 6) * NCHUNK) * 4096 + (size_t)r * 64;
    const float2* xj2 = (const float2*)xj_s;
    int tp = tid & 31;          // channel pair index: channels 2tp, 2tp+1
    int ks = tid >> 5;          // k parity for this warp
    for (int k = ks; k < 125; k += 2) {
        float a0 = 0.f, a1 = 0.f;
        int e0 = bstart[k], e1 = bstart[k + 1];
        for (int i = e0; i < e1; i++) {
            float2 wj = ws_srt[i];                       // broadcast LDS.64
            float2 x = xj2[__float_as_int(wj.y) + tp];   // conflict-free LDS.64
            a0 += wj.x * x.x;
            a1 += wj.x * x.y;
        }
        __nv_bfloat162 p = __floats2bfloat162_rn(a0, a1);
        *(uint32_t*)(Aout + tbase0 + (size_t)k * 4096 + ((2 * tp) ^ sw)) = *(uint32_t*)&p;
    }
    // root tile (k = 125): unscaled input features
    Aout[tbase0 + (size_t)125 * 4096 + (tid ^ sw)] =
        __float2bfloat16(xin[(size_t)xidx[n] * 64 + tid]);
}

// ---------------- bf16 mma GEMM, bulk-copy staging + ldmatrix, split-K -------
__global__ void __launch_bounds__(256) bmma_gemm_bulk(
    const __nv_bfloat16* __restrict__ At, const __nv_bfloat16* __restrict__ Bt,
    float* __restrict__ P, int N, size_t MN)
{
    extern __shared__ __align__(16) char dsm[];
    uint64_t* bar = (uint64_t*)dsm;                       // 3 barriers
    __nv_bfloat16* As = (__nv_bfloat16*)(dsm + 32);       // 3 x 8KB
    __nv_bfloat16* Bs = (__nv_bfloat16*)(dsm + 32 + 24576);

    int tid = threadIdx.x, warp = tid >> 5, lane = tid & 31;
    int wm = warp & 1, wn = warp >> 1;      // 2 x 4 warps
    int m0 = wm * 32, n0 = wn * 16;
    int g = lane >> 2, tg = lane & 3;

    int mb = blockIdx.x, nb = blockIdx.y;
    int z = blockIdx.z, nz = gridDim.z;
    int sIt = NCHUNK * z / nz, eIt = NCHUNK * (z + 1) / nz;
    int nIts = eIt - sIt;

    uint32_t barU = s2u(bar);
    uint32_t asU = s2u(As), bsU = s2u(Bs);

    // ldmatrix lane-constant geometry
    int ltile = lane >> 3, ltr = lane & 7;
    int aRb = m0 + (ltile & 1) * 8 + ltr;     // row base (+ mt*16)
    int aCsel = ltile >> 1;                   // 0 = k-lo 16B, 1 = k-hi
    int swrA = aRb & 7;                       // (aRb+16) & 7 == swrA
    uint32_t aRow0 = (uint32_t)(aRb * 128);   // bytes
    uint32_t aRow1 = aRow0 + 16 * 128;
    int bR = n0 + (ltile >> 1) * 8 + ltr;
    int bCsel = ltile & 1;
    int swrB = bR & 7;
    uint32_t bRow = (uint32_t)(bR * 128);

    if (tid == 0) {
#pragma unroll
        for (int s = 0; s < 3; s++)
            asm volatile("mbarrier.init.shared.b64 [%0], %1;"
                         :: "r"(barU + s * 8), "r"(1) : "memory");
    }
    __syncthreads();

    auto issue = [&](int li) {
        int s = li % 3;
        int kc = sIt + li;
        uint32_t b = barU + s * 8;
        asm volatile("mbarrier.arrive.expect_tx.shared.b64 _, [%0], %1;"
                     :: "r"(b), "r"(16384) : "memory");
        asm volatile(
            "cp.async.bulk.shared::cluster.global.mbarrier::complete_tx::bytes "
            "[%0], [%1], %2, [%3];"
            :: "r"(asU + s * 8192), "l"(At + ((size_t)mb * NCHUNK + kc) * 4096),
               "r"(8192), "r"(b) : "memory");
        asm volatile(
            "cp.async.bulk.shared::cluster.global.mbarrier::complete_tx::bytes "
            "[%0], [%1], %2, [%3];"
            :: "r"(bsU + s * 8192), "l"(Bt + ((size_t)nb * NCHUNK + kc) * 4096),
               "r"(8192), "r"(b) : "memory");
    };

    if (tid == 0) {
        int ni = nIts < 3 ? nIts : 3;
        for (int li = 0; li < ni; li++) issue(li);
    }

    float acc[2][2][4] = {};

    for (int li = 0; li < nIts; ++li) {
        int s = li % 3;
        int par = (li / 3) & 1;
        uint32_t b = barU + s * 8;
        asm volatile(
            "{\n\t.reg .pred P1;\n\t"
            "WL_%=: mbarrier.try_wait.parity.acquire.cta.shared::cta.b64 P1, [%0], %1, 0x989680;\n\t"
            "@P1 bra.uni WD_%=;\n\t"
            "bra.uni WL_%=;\n\t"
            "WD_%=:\n\t}"
            :: "r"(b), "r"(par) : "memory");

        uint32_t asBase = asU + s * 8192;
        uint32_t bsBase = bsU + s * 8192;
#pragma unroll
        for (int ksub = 0; ksub < 4; ksub++) {
            uint32_t af[2][4], bfr[2][2];
            uint32_t axo = (uint32_t)(((2 * ksub + aCsel) ^ swrA) << 4);
            uint32_t bxo = (uint32_t)(((2 * ksub + bCsel) ^ swrB) << 4);
            asm volatile("ldmatrix.sync.aligned.m8n8.x4.shared.b16 {%0,%1,%2,%3}, [%4];"
                : "=r"(af[0][0]), "=r"(af[0][1]), "=r"(af[0][2]), "=r"(af[0][3])
                : "r"(asBase + aRow0 + axo));
            asm volatile("ldmatrix.sync.aligned.m8n8.x4.shared.b16 {%0,%1,%2,%3}, [%4];"
                : "=r"(af[1][0]), "=r"(af[1][1]), "=r"(af[1][2]), "=r"(af[1][3])
                : "r"(asBase + aRow1 + axo));
            asm volatile("ldmatrix.sync.aligned.m8n8.x4.shared.b16 {%0,%1,%2,%3}, [%4];"
                : "=r"(bfr[0][0]), "=r"(bfr[0][1]), "=r"(bfr[1][0]), "=r"(bfr[1][1])
                : "r"(bsBase + bRow + bxo));
#pragma unroll
            for (int mt = 0; mt < 2; mt++)
#pragma unroll
                for (int nt = 0; nt < 2; nt++) {
                    asm volatile(
                        "mma.sync.aligned.m16n8k16.row.col.f32.bf16.bf16.f32 "
                        "{%0,%1,%2,%3}, {%4,%5,%6,%7}, {%8,%9}, {%0,%1,%2,%3};"
                        : "+f"(acc[mt][nt][0]), "+f"(acc[mt][nt][1]),
                          "+f"(acc[mt][nt][2]), "+f"(acc[mt][nt][3])
                        : "r"(af[mt][0]), "r"(af[mt][1]), "r"(af[mt][2]), "r"(af[mt][3]),
                          "r"(bfr[nt][0]), "r"(bfr[nt][1]));
                }
        }
        __syncthreads();
        if (tid == 0 && li + 3 < nIts) issue(li + 3);
    }

    // --- epilogue: raw fp32 partial stores ---
    float* Pz = P + (size_t)z * MN;
#pragma unroll
    for (int mt = 0; mt < 2; mt++) {
        size_t r0 = (size_t)mb * 64 + m0 + mt * 16 + g;
#pragma unroll
        for (int nt = 0; nt < 2; nt++) {
            int c = nb * 64 + n0 + nt * 8 + (tg << 1);
            *(float2*)(Pz + r0 * N + c) = make_float2(acc[mt][nt][0], acc[mt][nt][1]);
            *(float2*)(Pz + (r0 + 8) * N + c) = make_float2(acc[mt][nt][2], acc[mt][nt][3]);
        }
    }
}

// ---------------- split-K reduce + bias + ELU ----------------
__global__ void reduce_elu(const float* __restrict__ part, const float* __restrict__ bias,
                           float* __restrict__ outp, int MN, int N, int nsplit)
{
    int i = blockIdx.x * blockDim.x + threadIdx.x;   // float4 index
    if (i * 4 >= MN) return;
    float4 a = ((const float4*)part)[i];
    for (int zz = 1; zz < nsplit; zz++) {
        float4 b = ((const float4*)(part + (size_t)zz * MN))[i];
        a.x += b.x; a.y += b.y; a.z += b.z; a.w += b.w;
    }
    int c = (i * 4) % N;
    a.x = eluf(a.x + bias[c]);
    a.y = eluf(a.y + bias[c + 1]);
    a.z = eluf(a.z + bias[c + 2]);
    a.w = eluf(a.w + bias[c + 3]);
    ((float4*)outp)[i] = a;
}

// ---------------- pooling ----------------
__global__ void zero_pool(float* __restrict__ sums, float* __restrict__ cnt)
{
    int i = blockIdx.x * blockDim.x + threadIdx.x;
    if (i < N_CLOUDS * 128) sums[i] = 0.f;
    if (i < N_CLOUDS) cnt[i] = 0.f;
}

__global__ void pool_kernel(const float* __restrict__ x3, const int* __restrict__ batch,
                            const int* __restrict__ idx1, const int* __restrict__ idx2,
                            int n3, float* __restrict__ sums, float* __restrict__ cnt)
{
    int i = blockIdx.x * blockDim.x + threadIdx.x;
    if (i >= n3 * 128) return;
    int j = i >> 7, c = i & 127;
    int b = batch[idx1[idx2[j]]];
    atomicAdd(&sums[b * 128 + c], x3[i]);
    if (c == 0) atomicAdd(&cnt[b], 1.f);
}

// ---------------- MLP head + log_softmax, one block per cloud ----------------
__global__ void head_kernel(const float* __restrict__ sums, const float* __restrict__ cnt,
                            const float* __restrict__ lw1, const float* __restrict__ lb1,
                            const float* __restrict__ lw2, const float* __restrict__ lb2,
                            const float* __restrict__ lw3, const float* __restrict__ lb3,
                            float* __restrict__ out)
{
    __shared__ float g[128], h1[256], h2[256], lg[10];
    int b = blockIdx.x, tid = threadIdx.x;  // 256 threads
    if (tid < 128) g[tid] = sums[b * 128 + tid] / fmaxf(cnt[b], 1.f);
    __syncthreads();
    float a = lb1[tid];
    for (int c = 0; c < 128; c++) a += g[c] * lw1[c * 256 + tid];
    h1[tid] = eluf(a);
    __syncthreads();
    a = lb2[tid];
    for (int c = 0; c < 256; c++) a += h1[c] * lw2[c * 256 + tid];
    h2[tid] = eluf(a);
    __syncthreads();
    if (tid < 10) {
        a = lb3[tid];
        for (int c = 0; c < 256; c++) a += h2[c] * lw3[c * 10 + tid];
        lg[tid] = a;
    }
    __syncthreads();
    if (tid == 0) {
        float m = lg[0];
        for (int k = 1; k < 10; k++) m = fmaxf(m, lg[k]);
        float s = 0.f;
        for (int k = 0; k < 10; k++) s += expf(lg[k] - m);
        float ls = logf(s);
        for (int k = 0; k < 10; k++) out[b * 10 + k] = lg[k] - m - ls;
    }
}

// ---------------- host driver (graph-capturable: kernel launches only) -------
extern "C" void kernel_launch(void* const* d_in, const int* in_sizes, int n_in,
                              void* d_out, int out_size)
{
    const float* pos = (const float*)d_in[0];
    const int* batch = (const int*)d_in[1];
    const int* src1 = (const int*)d_in[2];
    const int* tgt1 = (const int*)d_in[3];
    const int* src2 = (const int*)d_in[4];
    const int* tgt2 = (const int*)d_in[5];
    const int* src3 = (const int*)d_in[6];
    const int* tgt3 = (const int*)d_in[7];
    const int* idx1 = (const int*)d_in[8];
    const int* idx2 = (const int*)d_in[9];
    const float* W1 = (const float*)d_in[10];
    const float* R1 = (const float*)d_in[11];
    const float* b1 = (const float*)d_in[12];
    const float* W2 = (const float*)d_in[13];
    const float* R2 = (const float*)d_in[14];
    const float* b2 = (const float*)d_in[15];
    const float* W3 = (const float*)d_in[16];
    const float* R3 = (const float*)d_in[17];
    const float* b3 = (const float*)d_in[18];
    const float* lw1 = (const float*)d_in[19];
    const float* lb1 = (const float*)d_in[20];
    const float* lw2 = (const float*)d_in[21];
    const float* lb2 = (const float*)d_in[22];
    const float* lw3 = (const float*)d_in[23];
    const float* lb3 = (const float*)d_in[24];
    float* out = (float*)d_out;

    int n1 = in_sizes[0] / 3;
    int E1 = in_sizes[2], E2 = in_sizes[4], E3 = in_sizes[6];
    int n2 = in_sizes[8], n3 = in_sizes[9];

    __nv_bfloat16 *pA, *pw2, *pw3;
    float *px1, *px2out, *px3out, *ppart, *pw1f, *ppool, *pcnt;
    cudaGetSymbolAddress((void**)&pA, g_A);
    cudaGetSymbolAddress((void**)&px1, g_x1);
    cudaGetSymbolAddress((void**)&px2out, g_x2out);
    cudaGetSymbolAddress((void**)&px3out, g_x3out);
    cudaGetSymbolAddress((void**)&ppart, g_part);
    cudaGetSymbolAddress((void**)&pw1f, g_w1f);
    cudaGetSymbolAddress((void**)&pw2, g_w2e);
    cudaGetSymbolAddress((void**)&pw3, g_w3e);
    cudaGetSymbolAddress((void**)&ppool, g_pool);
    cudaGetSymbolAddress((void**)&pcnt, g_cnt);

    const int SMEM_BULK = 32 + 3 * 8192 * 2;   // 49184 B
    cudaFuncSetAttribute(bmma_gemm_bulk,
                         cudaFuncAttributeMaxDynamicSharedMemorySize, SMEM_BULK);

    // merged weight prep
    {
        int tot = 128 * 64 + 64 * 8064 + 128 * 8064;
        prep_weights<<<(tot + 255) / 256, 256>>>(W1, R1, W2, R2, W3, R3, pw1f, pw2, pw3);
    }

    // ---- layer 1 fused (n1=32768, Cin=1, Cout=64, r=0.2) ----
    build_x1<<<n1 / 4, 128>>>(pos, src1, tgt1, E1, 1.f / 0.4f, pw1f, b1, px1);

    // ---- layer 2 (n2=16384, Cin=64, Cout=64, r=0.4), split-K=2 ----
    build_A64<<<n2, 64>>>(px1, idx1, pos, idx1, nullptr, src2, tgt2, E2, 1.f / 0.8f, pA);
    {
        size_t MN = (size_t)n2 * 64;
        bmma_gemm_bulk<<<dim3(n2 / 64, 1, 2), 256, SMEM_BULK>>>(pA, pw2, ppart, 64, MN);
        reduce_elu<<<(int)(MN / 4 + 255) / 256, 256>>>(ppart, b2, px2out, (int)MN, 64, 2);
    }

    // ---- layer 3 (n3=4096, Cin=64, Cout=128, r=1.0), split-K=4 ----
    build_A64<<<n3, 64>>>(px2out, idx2, pos, idx1, idx2, src3, tgt3, E3, 1.f / 2.0f, pA);
    {
        size_t MN = (size_t)n3 * 128;
        bmma_gemm_bulk<<<dim3(n3 / 64, 2, 4), 256, SMEM_BULK>>>(pA, pw3, ppart, 128, MN);
        reduce_elu<<<(int)(MN / 4 + 255) / 256, 256>>>(ppart, b3, px3out, (int)MN, 128, 4);
    }

    // ---- pool + head ----
    zero_pool<<<8, 256>>>(ppool, pcnt);
    pool_kernel<<<(n3 * 128 + 255) / 256, 256>>>(px3out, batch, idx1, idx2, n3, ppool, pcnt);
    head_kernel<<<N_CLOUDS, 256>>>(ppool, pcnt, lw1, lb1, lw2, lb2, lw3, lb3, out);
}

// round 17
// speedup vs baseline: 1.1224x; 1.1224x over previous
#include <cuda_runtime.h>
#include <cuda_bf16.h>
#include <math.h>
#include <stdint.h>

#define N_CLOUDS 16
#define NCHUNK 126   // K = 8064 = 126 chunks of 64

// ---------------- static scratch (no allocations allowed) ----------------
// A & W stored as contiguous 8KB tiles: tile(mb,kc) = 64 rows x 64 halfs,
// pre-swizzled: half h at row r lives at r*64 + (h ^ ((r&7)<<3)).
__device__ __align__(16) __nv_bfloat16 g_A[(size_t)16384 * 8064];
__device__ __align__(16) float g_x1[32768 * 64];
__device__ __align__(16) float g_x2out[16384 * 64];
__device__ __align__(16) float g_x3out[4096 * 128];
__device__ __align__(16) float g_part[2097152];            // split-K partials (8MB)
__device__ __align__(16) float g_w1f[128 * 64];            // fp32 [k][o] for fused L1
__device__ __align__(16) __nv_bfloat16 g_w2e[64 * 8064];   // tiled [1][126] tiles
__device__ __align__(16) __nv_bfloat16 g_w3e[128 * 8064];  // tiled [2][126] tiles
__device__ __align__(16) float g_pool[N_CLOUDS * 128];
__device__ __align__(16) float g_cnt[N_CLOUDS];

__device__ __forceinline__ int lowerb(const int* __restrict__ a, int n, int v) {
    int lo = 0, hi = n;
    while (lo < hi) { int m = (lo + hi) >> 1; if (a[m] < v) lo = m + 1; else hi = m; }
    return lo;
}

__device__ __forceinline__ float eluf(float v) { return v > 0.f ? v : expm1f(v); }

__device__ __forceinline__ uint32_t s2u(const void* p) {
    return (uint32_t)__cvta_generic_to_shared(p);
}

// ---------------- merged weight prep: w1f (fp32) + w2e/w3e tiled bf16 --------
__global__ void prep_weights(const float* __restrict__ W1, const float* __restrict__ R1,
                             const float* __restrict__ W2, const float* __restrict__ R2,
                             const float* __restrict__ W3, const float* __restrict__ R3,
                             float* __restrict__ w1f, __nv_bfloat16* __restrict__ w2e,
                             __nv_bfloat16* __restrict__ w3e)
{
    const int N1 = 128 * 64, N2 = 64 * 8064, N3 = 128 * 8064;
    int i = blockIdx.x * blockDim.x + threadIdx.x;
    if (i < N1) {
        int k = i >> 6, c = i & 63;
        float v = 0.f;
        if (k < 125) v = W1[k * 64 + c];
        else if (k == 125) v = R1[c];
        w1f[i] = v;
        return;
    }
    i -= N1;
    if (i < N2) {
        int k = i / 64, c = i - k * 64;          // k in K-dim, c = out channel
        float v = 0.f;
        if (k < 8000) v = W2[k * 64 + c];
        else if (k < 8064) v = R2[(k - 8000) * 64 + c];
        int kc = k >> 6, kh = k & 63, r = c & 63;
        w2e[(size_t)kc * 4096 + r * 64 + (kh ^ ((r & 7) << 3))] = __float2bfloat16(v);
        return;
    }
    i -= N2;
    if (i < N3) {
        int k = i / 128, c = i - k * 128;
        float v = 0.f;
        if (k < 8000) v = W3[k * 128 + c];
        else if (k < 8064) v = R3[(k - 8000) * 128 + c];
        int kc = k >> 6, kh = k & 63, nb = c >> 6, r = c & 63;
        w3e[((size_t)nb * NCHUNK + kc) * 4096 + r * 64 + (kh ^ ((r & 7) << 3))] =
            __float2bfloat16(v);
    }
}

// ---------------- layer 1 fused: A build (Cin=1) + 128x64 matvec + ELU -------
// R15 version: per-thread W loop (L1-resident W1f), 4 warps = 4 nodes, occ ~85%.
__global__ void __launch_bounds__(128) build_x1(
    const float* __restrict__ pos, const int* __restrict__ src,
    const int* __restrict__ tgt, int nE, float inv2r,
    const float* __restrict__ W1f, const float* __restrict__ b1,
    float* __restrict__ x1)
{
    __shared__ float A[4][128];
    int warp = threadIdx.x >> 5, lane = threadIdx.x & 31;
    int n = blockIdx.x * 4 + warp;
    float* Aw = A[warp];
    Aw[lane] = 0.f; Aw[lane + 32] = 0.f; Aw[lane + 64] = 0.f; Aw[lane + 96] = 0.f;
    __syncwarp();
    int s0 = lowerb(tgt, nE, n);
    int s1 = lowerb(tgt, nE, n + 1);
    float tx = pos[n * 3 + 0], ty = pos[n * 3 + 1], tz = pos[n * 3 + 2];
    for (int e = s0 + lane; e < s1; e += 32) {
        int sN = src[e];
        float px = fminf(fmaxf((tx - pos[sN * 3 + 0]) * inv2r + 0.5f, 0.f), 1.f) * 4.f;
        float py = fminf(fmaxf((ty - pos[sN * 3 + 1]) * inv2r + 0.5f, 0.f), 1.f) * 4.f;
        float pz = fminf(fmaxf((tz - pos[sN * 3 + 2]) * inv2r + 0.5f, 0.f), 1.f) * 4.f;
        float bx = floorf(px), by = floorf(py), bz = floorf(pz);
        float fx = px - bx, fy = py - by, fz = pz - bz;
        int ix = (int)bx, iy = (int)by, iz = (int)bz;
#pragma unroll
        for (int s = 0; s < 8; s++) {
            int b0 = s & 1, b1i = (s >> 1) & 1, b2 = s >> 2;
            float w = (b0 ? fx : 1.f - fx) * (b1i ? fy : 1.f - fy) * (b2 ? fz : 1.f - fz);
            int wi = min(ix + b0, 4) + 5 * min(iy + b1i, 4) + 25 * min(iz + b2, 4);
            atomicAdd(&Aw[wi], w);
        }
    }
    __syncwarp();
    float invd = 1.f / fmaxf((float)(s1 - s0), 1.f);
    int o1 = lane, o2 = lane + 32;
    float acc1 = 0.f, acc2 = 0.f;
#pragma unroll 5
    for (int k = 0; k < 125; k++) {
        float a = Aw[k];
        acc1 += a * W1f[k * 64 + o1];
        acc2 += a * W1f[k * 64 + o2];
    }
    acc1 = acc1 * invd + W1f[125 * 64 + o1] + b1[o1];   // root (x==1) + bias
    acc2 = acc2 * invd + W1f[125 * 64 + o2] + b1[o2];
    x1[(size_t)n * 64 + o1] = eluf(acc1);
    x1[(size_t)n * 64 + o2] = eluf(acc2);
}

// ---------------- layers 2/3 A build: tiled+swizzled A output ----------------
__global__ void __launch_bounds__(64) build_A64(
    const float* __restrict__ xin, const int* __restrict__ xidx,
    const float* __restrict__ pos, const int* __restrict__ pidx1,
    const int* __restrict__ pidx2,
    const int* __restrict__ src, const int* __restrict__ tgt, int nE,
    float inv2r, __nv_bfloat16* __restrict__ Aout)
{
    __shared__ float xj_s[32 * 64];        // 8KB fp32, float2-aligned
    __shared__ float tw[256];
    __shared__ unsigned char twi[256];
    __shared__ float2 ws_srt[256];         // (w, bitcast(j*32))
    __shared__ int cnts[128];              // 125 used + 3 zero pad (scan safety)
    __shared__ int bstart[126];
    __shared__ int cursor[125];
    __shared__ int esrc_s[32];

    int n = blockIdx.x, tid = threadIdx.x;   // 64 threads
    cnts[tid] = 0; cnts[tid + 64] = 0;       // zero all 128
    int s0 = lowerb(tgt, nE, n);
    int s1 = lowerb(tgt, nE, n + 1);
    int cnt = min(s1 - s0, 32);              // max_nb = 32
    float invd = 1.f / fmaxf((float)cnt, 1.f);
    int pn = pidx2 ? pidx1[pidx2[n]] : pidx1[n];
    float tx = pos[pn * 3 + 0], ty = pos[pn * 3 + 1], tz = pos[pn * 3 + 2];
    __syncthreads();
    if (tid < cnt) {
        int sN = src[s0 + tid];
        esrc_s[tid] = xidx[sN];              // resolved x row
        int ps = pidx2 ? pidx1[pidx2[sN]] : pidx1[sN];
        float px = fminf(fmaxf((tx - pos[ps * 3 + 0]) * inv2r + 0.5f, 0.f), 1.f) * 4.f;
        float py = fminf(fmaxf((ty - pos[ps * 3 + 1]) * inv2r + 0.5f, 0.f), 1.f) * 4.f;
        float pz = fminf(fmaxf((tz - pos[ps * 3 + 2]) * inv2r + 0.5f, 0.f), 1.f) * 4.f;
        float bx = floorf(px), by = floorf(py), bz = floorf(pz);
        float fx = px - bx, fy = py - by, fz = pz - bz;
        int ix = (int)bx, iy = (int)by, iz = (int)bz;
#pragma unroll
        for (int s = 0; s < 8; s++) {
            int b0 = s & 1, b1 = (s >> 1) & 1, b2 = s >> 2;
            float w = (b0 ? fx : 1.f - fx) * (b1 ? fy : 1.f - fy) * (b2 ? fz : 1.f - fz);
            int wi = min(ix + b0, 4) + 5 * min(iy + b1, 4) + 25 * min(iz + b2, 4);
            tw[tid * 8 + s] = w * invd;       // fold degree normalization
            twi[tid * 8 + s] = (unsigned char)wi;
            atomicAdd(&cnts[wi], 1);
        }
    }
    __syncthreads();
    // warp-scan prefix over 128 buckets (warp 0; 4 buckets/lane; 125..127 = 0)
    if (tid < 32) {
        int b0i = tid * 4;
        int v0 = cnts[b0i], v1 = cnts[b0i + 1], v2 = cnts[b0i + 2], v3 = cnts[b0i + 3];
        int s = v0 + v1 + v2 + v3;
#pragma unroll
        for (int off = 1; off < 32; off <<= 1) {
            int t = __shfl_up_sync(0xffffffff, s, off);
            if (tid >= off) s += t;
        }
        int base = s - (v0 + v1 + v2 + v3);
        bstart[b0i] = base;
        if (b0i + 1 <= 125) bstart[b0i + 1] = base + v0;
        if (b0i + 2 <= 125) bstart[b0i + 2] = base + v0 + v1;
        if (b0i + 3 <= 125) bstart[b0i + 3] = base + v0 + v1 + v2;
    }
    __syncthreads();
    for (int i = tid; i < 125; i += 64) cursor[i] = bstart[i];
    __syncthreads();
    if (tid < cnt) {
#pragma unroll
        for (int s = 0; s < 8; s++) {
            int wi = twi[tid * 8 + s];
            int p = atomicAdd(&cursor[wi], 1);
            ws_srt[p] = make_float2(tw[tid * 8 + s], __int_as_float(tid * 32));
        }
    }
    // stage xj rows — 4-way unrolled for MLP
    {
        int j = 0;
        for (; j + 4 <= cnt; j += 4) {
            float v0 = xin[(size_t)esrc_s[j] * 64 + tid];
            float v1 = xin[(size_t)esrc_s[j + 1] * 64 + tid];
            float v2 = xin[(size_t)esrc_s[j + 2] * 64 + tid];
            float v3 = xin[(size_t)esrc_s[j + 3] * 64 + tid];
            xj_s[j * 64 + tid] = v0;
            xj_s[(j + 1) * 64 + tid] = v1;
            xj_s[(j + 2) * 64 + tid] = v2;
            xj_s[(j + 3) * 64 + tid] = v3;
        }
        for (; j < cnt; j++)
            xj_s[j * 64 + tid] = xin[(size_t)esrc_s[j] * 64 + tid];
    }
    __syncthreads();

    // tiled + swizzled output
    int r = n & 63;
    int sw = (r & 7) << 3;
    size_t tbase0 = ((size_t)(n >> 6) * NCHUNK) * 4096 + (size_t)r * 64;
    const float2* xj2 = (const float2*)xj_s;
    int tp = tid & 31;          // channel pair index: channels 2tp, 2tp+1
    int ks = tid >> 5;          // k parity for this warp
    for (int k = ks; k < 125; k += 2) {
        float a0 = 0.f, a1 = 0.f;
        int e0 = bstart[k], e1 = bstart[k + 1];
        for (int i = e0; i < e1; i++) {
            float2 wj = ws_srt[i];                       // broadcast LDS.64
            float2 x = xj2[__float_as_int(wj.y) + tp];   // conflict-free LDS.64
            a0 += wj.x * x.x;
            a1 += wj.x * x.y;
        }
        __nv_bfloat162 p = __floats2bfloat162_rn(a0, a1);
        *(uint32_t*)(Aout + tbase0 + (size_t)k * 4096 + ((2 * tp) ^ sw)) = *(uint32_t*)&p;
    }
    // root tile (k = 125): unscaled input features
    Aout[tbase0 + (size_t)125 * 4096 + (tid ^ sw)] =
        __float2bfloat16(xin[(size_t)xidx[n] * 64 + tid]);
}

// ---------------- bf16 mma GEMM, bulk-copy staging + ldmatrix, split-K -------
__global__ void __launch_bounds__(256) bmma_gemm_bulk(
    const __nv_bfloat16* __restrict__ At, const __nv_bfloat16* __restrict__ Bt,
    float* __restrict__ P, int N, size_t MN)
{
    extern __shared__ __align__(16) char dsm[];
    uint64_t* bar = (uint64_t*)dsm;                       // 3 barriers
    __nv_bfloat16* As = (__nv_bfloat16*)(dsm + 32);       // 3 x 8KB
    __nv_bfloat16* Bs = (__nv_bfloat16*)(dsm + 32 + 24576);

    int tid = threadIdx.x, warp = tid >> 5, lane = tid & 31;
    int wm = warp & 1, wn = warp >> 1;      // 2 x 4 warps
    int m0 = wm * 32, n0 = wn * 16;
    int g = lane >> 2, tg = lane & 3;

    int mb = blockIdx.x, nb = blockIdx.y;
    int z = blockIdx.z, nz = gridDim.z;
    int sIt = NCHUNK * z / nz, eIt = NCHUNK * (z + 1) / nz;
    int nIts = eIt - sIt;

    uint32_t barU = s2u(bar);
    uint32_t asU = s2u(As), bsU = s2u(Bs);

    // ldmatrix lane-constant geometry
    int ltile = lane >> 3, ltr = lane & 7;
    int aRb = m0 + (ltile & 1) * 8 + ltr;     // row base (+ mt*16)
    int aCsel = ltile >> 1;                   // 0 = k-lo 16B, 1 = k-hi
    int swrA = aRb & 7;                       // (aRb+16) & 7 == swrA
    uint32_t aRow0 = (uint32_t)(aRb * 128);   // bytes
    uint32_t aRow1 = aRow0 + 16 * 128;
    int bR = n0 + (ltile >> 1) * 8 + ltr;
    int bCsel = ltile & 1;
    int swrB = bR & 7;
    uint32_t bRow = (uint32_t)(bR * 128);

    if (tid == 0) {
#pragma unroll
        for (int s = 0; s < 3; s++)
            asm volatile("mbarrier.init.shared.b64 [%0], %1;"
                         :: "r"(barU + s * 8), "r"(1) : "memory");
    }
    __syncthreads();

    auto issue = [&](int li) {
        int s = li % 3;
        int kc = sIt + li;
        uint32_t b = barU + s * 8;
        asm volatile("mbarrier.arrive.expect_tx.shared.b64 _, [%0], %1;"
                     :: "r"(b), "r"(16384) : "memory");
        asm volatile(
            "cp.async.bulk.shared::cluster.global.mbarrier::complete_tx::bytes "
            "[%0], [%1], %2, [%3];"
            :: "r"(asU + s * 8192), "l"(At + ((size_t)mb * NCHUNK + kc) * 4096),
               "r"(8192), "r"(b) : "memory");
        asm volatile(
            "cp.async.bulk.shared::cluster.global.mbarrier::complete_tx::bytes "
            "[%0], [%1], %2, [%3];"
            :: "r"(bsU + s * 8192), "l"(Bt + ((size_t)nb * NCHUNK + kc) * 4096),
               "r"(8192), "r"(b) : "memory");
    };

    if (tid == 0) {
        int ni = nIts < 3 ? nIts : 3;
        for (int li = 0; li < ni; li++) issue(li);
    }

    float acc[2][2][4] = {};

    for (int li = 0; li < nIts; ++li) {
        int s = li % 3;
        int par = (li / 3) & 1;
        uint32_t b = barU + s * 8;
        asm volatile(
            "{\n\t.reg .pred P1;\n\t"
            "WL_%=: mbarrier.try_wait.parity.acquire.cta.shared::cta.b64 P1, [%0], %1, 0x989680;\n\t"
            "@P1 bra.uni WD_%=;\n\t"
            "bra.uni WL_%=;\n\t"
            "WD_%=:\n\t}"
            :: "r"(b), "r"(par) : "memory");

        uint32_t asBase = asU + s * 8192;
        uint32_t bsBase = bsU + s * 8192;
#pragma unroll
        for (int ksub = 0; ksub < 4; ksub++) {
            uint32_t af[2][4], bfr[2][2];
            uint32_t axo = (uint32_t)(((2 * ksub + aCsel) ^ swrA) << 4);
            uint32_t bxo = (uint32_t)(((2 * ksub + bCsel) ^ swrB) << 4);
            asm volatile("ldmatrix.sync.aligned.m8n8.x4.shared.b16 {%0,%1,%2,%3}, [%4];"
                : "=r"(af[0][0]), "=r"(af[0][1]), "=r"(af[0][2]), "=r"(af[0][3])
                : "r"(asBase + aRow0 + axo));
            asm volatile("ldmatrix.sync.aligned.m8n8.x4.shared.b16 {%0,%1,%2,%3}, [%4];"
                : "=r"(af[1][0]), "=r"(af[1][1]), "=r"(af[1][2]), "=r"(af[1][3])
                : "r"(asBase + aRow1 + axo));
            asm volatile("ldmatrix.sync.aligned.m8n8.x4.shared.b16 {%0,%1,%2,%3}, [%4];"
                : "=r"(bfr[0][0]), "=r"(bfr[0][1]), "=r"(bfr[1][0]), "=r"(bfr[1][1])
                : "r"(bsBase + bRow + bxo));
#pragma unroll
            for (int mt = 0; mt < 2; mt++)
#pragma unroll
                for (int nt = 0; nt < 2; nt++) {
                    asm volatile(
                        "mma.sync.aligned.m16n8k16.row.col.f32.bf16.bf16.f32 "
                        "{%0,%1,%2,%3}, {%4,%5,%6,%7}, {%8,%9}, {%0,%1,%2,%3};"
                        : "+f"(acc[mt][nt][0]), "+f"(acc[mt][nt][1]),
                          "+f"(acc[mt][nt][2]), "+f"(acc[mt][nt][3])
                        : "r"(af[mt][0]), "r"(af[mt][1]), "r"(af[mt][2]), "r"(af[mt][3]),
                          "r"(bfr[nt][0]), "r"(bfr[nt][1]));
                }
        }
        __syncthreads();
        if (tid == 0 && li + 3 < nIts) issue(li + 3);
    }

    // --- epilogue: raw fp32 partial stores ---
    float* Pz = P + (size_t)z * MN;
#pragma unroll
    for (int mt = 0; mt < 2; mt++) {
        size_t r0 = (size_t)mb * 64 + m0 + mt * 16 + g;
#pragma unroll
        for (int nt = 0; nt < 2; nt++) {
            int c = nb * 64 + n0 + nt * 8 + (tg << 1);
            *(float2*)(Pz + r0 * N + c) = make_float2(acc[mt][nt][0], acc[mt][nt][1]);
            *(float2*)(Pz + (r0 + 8) * N + c) = make_float2(acc[mt][nt][2], acc[mt][nt][3]);
        }
    }
}

// ---------------- split-K reduce + bias + ELU ----------------
__global__ void reduce_elu(const float* __restrict__ part, const float* __restrict__ bias,
                           float* __restrict__ outp, int MN, int N, int nsplit)
{
    int i = blockIdx.x * blockDim.x + threadIdx.x;   // float4 index
    if (i * 4 >= MN) return;
    float4 a = ((const float4*)part)[i];
    for (int zz = 1; zz < nsplit; zz++) {
        float4 b = ((const float4*)(part + (size_t)zz * MN))[i];
        a.x += b.x; a.y += b.y; a.z += b.z; a.w += b.w;
    }
    int c = (i * 4) % N;
    a.x = eluf(a.x + bias[c]);
    a.y = eluf(a.y + bias[c + 1]);
    a.z = eluf(a.z + bias[c + 2]);
    a.w = eluf(a.w + bias[c + 3]);
    ((float4*)outp)[i] = a;
}

// ---------------- pooling ----------------
__global__ void zero_pool(float* __restrict__ sums, float* __restrict__ cnt)
{
    int i = blockIdx.x * blockDim.x + threadIdx.x;
    if (i < N_CLOUDS * 128) sums[i] = 0.f;
    if (i < N_CLOUDS) cnt[i] = 0.f;
}

__global__ void pool_kernel(const float* __restrict__ x3, const int* __restrict__ batch,
                            const int* __restrict__ idx1, const int* __restrict__ idx2,
                            int n3, float* __restrict__ sums, float* __restrict__ cnt)
{
    int i = blockIdx.x * blockDim.x + threadIdx.x;
    if (i >= n3 * 128) return;
    int j = i >> 7, c = i & 127;
    int b = batch[idx1[idx2[j]]];
    atomicAdd(&sums[b * 128 + c], x3[i]);
    if (c == 0) atomicAdd(&cnt[b], 1.f);
}

// ---------------- MLP head + log_softmax, one block per cloud ----------------
__global__ void head_kernel(const float* __restrict__ sums, const float* __restrict__ cnt,
                            const float* __restrict__ lw1, const float* __restrict__ lb1,
                            const float* __restrict__ lw2, const float* __restrict__ lb2,
                            const float* __restrict__ lw3, const float* __restrict__ lb3,
                            float* __restrict__ out)
{
    __shared__ float g[128], h1[256], h2[256], lg[10];
    int b = blockIdx.x, tid = threadIdx.x;  // 256 threads
    if (tid < 128) g[tid] = sums[b * 128 + tid] / fmaxf(cnt[b], 1.f);
    __syncthreads();
    float a = lb1[tid];
    for (int c = 0; c < 128; c++) a += g[c] * lw1[c * 256 + tid];
    h1[tid] = eluf(a);
    __syncthreads();
    a = lb2[tid];
    for (int c = 0; c < 256; c++) a += h1[c] * lw2[c * 256 + tid];
    h2[tid] = eluf(a);
    __syncthreads();
    if (tid < 10) {
        a = lb3[tid];
        for (int c = 0; c < 256; c++) a += h2[c] * lw3[c * 10 + tid];
        lg[tid] = a;
    }
    __syncthreads();
    if (tid == 0) {
        float m = lg[0];
        for (int k = 1; k < 10; k++) m = fmaxf(m, lg[k]);
        float s = 0.f;
        for (int k = 0; k < 10; k++) s += expf(lg[k] - m);
        float ls = logf(s);
        for (int k = 0; k < 10; k++) out[b * 10 + k] = lg[k] - m - ls;
    }
}

// ---------------- host driver (graph-capturable: kernel launches only) -------
extern "C" void kernel_launch(void* const* d_in, const int* in_sizes, int n_in,
                              void* d_out, int out_size)
{
    const float* pos = (const float*)d_in[0];
    const int* batch = (const int*)d_in[1];
    const int* src1 = (const int*)d_in[2];
    const int* tgt1 = (const int*)d_in[3];
    const int* src2 = (const int*)d_in[4];
    const int* tgt2 = (const int*)d_in[5];
    const int* src3 = (const int*)d_in[6];
    const int* tgt3 = (const int*)d_in[7];
    const int* idx1 = (const int*)d_in[8];
    const int* idx2 = (const int*)d_in[9];
    const float* W1 = (const float*)d_in[10];
    const float* R1 = (const float*)d_in[11];
    const float* b1 = (const float*)d_in[12];
    const float* W2 = (const float*)d_in[13];
    const float* R2 = (const float*)d_in[14];
    const float* b2 = (const float*)d_in[15];
    const float* W3 = (const float*)d_in[16];
    const float* R3 = (const float*)d_in[17];
    const float* b3 = (const float*)d_in[18];
    const float* lw1 = (const float*)d_in[19];
    const float* lb1 = (const float*)d_in[20];
    const float* lw2 = (const float*)d_in[21];
    const float* lb2 = (const float*)d_in[22];
    const float* lw3 = (const float*)d_in[23];
    const float* lb3 = (const float*)d_in[24];
    float* out = (float*)d_out;

    int n1 = in_sizes[0] / 3;
    int E1 = in_sizes[2], E2 = in_sizes[4], E3 = in_sizes[6];
    int n2 = in_sizes[8], n3 = in_sizes[9];

    __nv_bfloat16 *pA, *pw2, *pw3;
    float *px1, *px2out, *px3out, *ppart, *pw1f, *ppool, *pcnt;
    cudaGetSymbolAddress((void**)&pA, g_A);
    cudaGetSymbolAddress((void**)&px1, g_x1);
    cudaGetSymbolAddress((void**)&px2out, g_x2out);
    cudaGetSymbolAddress((void**)&px3out, g_x3out);
    cudaGetSymbolAddress((void**)&ppart, g_part);
    cudaGetSymbolAddress((void**)&pw1f, g_w1f);
    cudaGetSymbolAddress((void**)&pw2, g_w2e);
    cudaGetSymbolAddress((void**)&pw3, g_w3e);
    cudaGetSymbolAddress((void**)&ppool, g_pool);
    cudaGetSymbolAddress((void**)&pcnt, g_cnt);

    const int SMEM_BULK = 32 + 3 * 8192 * 2;   // 49184 B
    cudaFuncSetAttribute(bmma_gemm_bulk,
                         cudaFuncAttributeMaxDynamicSharedMemorySize, SMEM_BULK);

    // merged weight prep
    {
        int tot = 128 * 64 + 64 * 8064 + 128 * 8064;
        prep_weights<<<(tot + 255) / 256, 256>>>(W1, R1, W2, R2, W3, R3, pw1f, pw2, pw3);
    }

    // ---- layer 1 fused (n1=32768, Cin=1, Cout=64, r=0.2) ----
    build_x1<<<n1 / 4, 128>>>(pos, src1, tgt1, E1, 1.f / 0.4f, pw1f, b1, px1);

    // ---- layer 2 (n2=16384, Cin=64, Cout=64, r=0.4), split-K=2 ----
    build_A64<<<n2, 64>>>(px1, idx1, pos, idx1, nullptr, src2, tgt2, E2, 1.f / 0.8f, pA);
    {
        size_t MN = (size_t)n2 * 64;
        bmma_gemm_bulk<<<dim3(n2 / 64, 1, 2), 256, SMEM_BULK>>>(pA, pw2, ppart, 64, MN);
        reduce_elu<<<(int)(MN / 4 + 255) / 256, 256>>>(ppart, b2, px2out, (int)MN, 64, 2);
    }

    // ---- layer 3 (n3=4096, Cin=64, Cout=128, r=1.0), split-K=4 ----
    build_A64<<<n3, 64>>>(px2out, idx2, pos, idx1, idx2, src3, tgt3, E3, 1.f / 2.0f, pA);
    {
        size_t MN = (size_t)n3 * 128;
        bmma_gemm_bulk<<<dim3(n3 / 64, 2, 4), 256, SMEM_BULK>>>(pA, pw3, ppart, 128, MN);
        reduce_elu<<<(int)(MN / 4 + 255) / 256, 256>>>(ppart, b3, px3out, (int)MN, 128, 4);
    }

    // ---- pool + head ----
    zero_pool<<<8, 256>>>(ppool, pcnt);
    pool_kernel<<<(n3 * 128 + 255) / 256, 256>>>(px3out, batch, idx1, idx2, n3, ppool, pcnt);
    head_kernel<<<N_CLOUDS, 256>>>(ppool, pcnt, lw1, lb1, lw2, lb2, lw3, lb3, out);
}